// round 16
// baseline (speedup 1.0000x reference)
#include <cuda_runtime.h>
#include <math.h>

#define B_   16
#define H_   128
#define W_   64
#define T_   64
#define NLOC (B_ * H_ * W_)

// Scratch: spike bitmasks (1 bit per timestep)
__device__ unsigned long long g_xbits[NLOC];
__device__ unsigned long long g_s1bits[NLOC];

// ---------------------------------------------------------------------------
// Kernel 0: pack input floats (exactly 0.0 / 1.0) into per-neuron bitmasks.
// ---------------------------------------------------------------------------
__global__ void __launch_bounds__(256) pack_kernel(const float* __restrict__ in) {
    const int lane = threadIdx.x & 31;
    const int w0   = threadIdx.x & 32;
    const int h    = blockIdx.x * 4 + threadIdx.y;
    const int b    = blockIdx.y;
    const int loc0 = (b * H_ + h) * W_ + w0;
    const size_t gbase = (size_t)loc0 * T_;

    unsigned lo = 0u, hi = 0u;
#pragma unroll
    for (int i = 0; i < 64; ++i) {
        float v = in[gbase + i * 32 + lane];
        unsigned bal = __ballot_sync(0xffffffffu, v != 0.0f);
        if (lane == (i >> 1)) {
            if (i & 1) hi = bal; else lo = bal;
        }
    }
    g_xbits[loc0 + lane] = ((unsigned long long)hi << 32) | (unsigned long long)lo;
}

// ---------------------------------------------------------------------------
// Fused layer kernel — R15 structure; ONE change: psp fill uses a 32-bit
// spike window (bit 15-j / 7-j == spike(t-j)) so each tap is a LOP3-imm
// predicate + predicated FADD. Same adds, same descending-j order ->
// bit-identical psp values.
// Refractory: IIR(2) fast path + warp-voted EXACT fallback (validated R15).
// Winograd F(2x2,3x3) op sequence identical to R6/R7/R9.
// ---------------------------------------------------------------------------
template <int LAYER>
__global__ void __launch_bounds__(128) fused_kernel(const float* __restrict__ wconv,
                                                    float* __restrict__ out) {
    constexpr int   FIRN  = (LAYER == 0) ? 8 : 16;
    constexpr int   NT    = FIRN - 1;        // taps j = NT..1
    constexpr int   JMAX  = (LAYER == 0) ? 17 : 35;
    constexpr float THETA = (LAYER == 0) ? 30.0f : 50.0f;
    constexpr float EPS   = 0.015625f;       // 2^-6, validated R13/R15
    constexpr int   HR    = 10;              // halo rows (8 + 2)
    constexpr int   HC    = 66;              // halo cols (64 + 2)
    constexpr int   NH    = HR * HC;         // 660
    constexpr int   TC    = 8;               // timestep chunk

    __shared__ __align__(16) float s_buf[TC][HR][72];   // psp tile, padded
    __shared__ float s_kk[FIRN];
    __shared__ float s_rk[JMAX + 1];
    __shared__ float s_w[9];

    const int tid = threadIdx.x;
    const int h0  = blockIdx.x * 8;
    const int b   = blockIdx.y;

    // --- taps in double, matching numpy exactly ---
    {
        const double tau   = (LAYER == 0) ? 1.0 : 2.0;
        const double rmult = (LAYER == 0) ? -60.0 : -100.0;  // -2*theta*scale_ref
        if (tid < FIRN) {
            double td = (double)tid;
            s_kk[tid] = (float)(((1.0 * td) / tau) * exp(1.0 - td / tau));
        }
        if (tid <= JMAX) {
            double td = (double)tid;
            double v  = ((rmult * td) / tau) * exp(1.0 - td / tau);
            s_rk[tid] = (tid == 0) ? 0.0f : (float)v;
        }
        if (tid < 9) s_w[tid] = wconv[tid];
    }
    __syncthreads();

    // IIR constants (approximation only; decisions guarded by ε-band)
    const double a_d = exp((LAYER == 0) ? -1.0 : -0.5);
    const float  A1  = (float)(2.0 * a_d);
    const float  A2  = (float)(-a_d * a_d);
    const float  RK1 = s_rk[1];

    float kk[FIRN];
#pragma unroll
    for (int k = 0; k < FIRN; ++k) kk[k] = s_kk[k];

    // --- weight transform U = G g G^T, exact-half form (identical to R6) ---
    float U[4][4];
    {
        float q[4][3];
#pragma unroll
        for (int j = 0; j < 3; ++j) {
            float g0 = s_w[j], g1 = s_w[3 + j], g2 = s_w[6 + j];
            float s  = __fadd_rn(g0, g2);
            q[0][j] = g0;
            q[1][j] = __fmul_rn(0.5f, __fadd_rn(s, g1));
            q[2][j] = __fmul_rn(0.5f, __fsub_rn(s, g1));
            q[3][j] = g2;
        }
#pragma unroll
        for (int i = 0; i < 4; ++i) {
            float q0 = q[i][0], q1 = q[i][1], q2 = q[i][2];
            float s  = __fadd_rn(q0, q2);
            U[i][0] = q0;
            U[i][1] = __fmul_rn(0.5f, __fadd_rn(s, q1));
            U[i][2] = __fmul_rn(0.5f, __fsub_rn(s, q1));
            U[i][3] = q2;
        }
    }

    // --- halo bitmask load: rows h0-1..h0+8, cols -1..64, zeros outside ---
    const unsigned long long* bits = (LAYER == 0) ? g_xbits : g_s1bits;
    unsigned long long hm[6];
    int soff[6];
#pragma unroll
    for (int k = 0; k < 6; ++k) {
        int l  = tid + 128 * k;
        int hr = l / HC, hc = l % HC;
        bool valid = (l < NH);
        int grow = h0 - 1 + hr, gcol = hc - 1;
        unsigned long long v = 0ull;
        if (valid && (unsigned)grow < (unsigned)H_ && (unsigned)gcol < (unsigned)W_)
            v = bits[(b * H_ + grow) * W_ + gcol];
        hm[k]   = v;
        soff[k] = valid ? hr * 72 + hc : 9 * 72 + 66;   // pad slot if invalid
    }

    const int tr   = tid >> 5;           // tile row 0..3
    const int tcix = tid & 31;           // tile col 0..31
    const int row0 = 2 * tr;
    const int col0 = 2 * tcix;

    unsigned long long sm[4]  = {0ull, 0ull, 0ull, 0ull};
    unsigned long long win[4] = {0ull, 0ull, 0ull, 0ull};
    float r1[4] = {0.0f, 0.0f, 0.0f, 0.0f};
    float r2[4] = {0.0f, 0.0f, 0.0f, 0.0f};
    float sf[4] = {0.0f, 0.0f, 0.0f, 0.0f};

    for (int tb = 0; tb < T_; tb += TC) {
        // ---- psp fill: 32-bit window, bit NT-j == spike(t-j) ----
#pragma unroll
        for (int k = 0; k < 6; ++k) {
            unsigned long long mk = hm[k];
            float* dst = &s_buf[0][0][0] + soff[k];
#pragma unroll 4
            for (int dt = 0; dt < TC; ++dt) {
                int t = tb + dt;
                unsigned w = (t >= NT) ? (unsigned)(mk >> (t - NT))
                                       : (unsigned)(mk << (NT - t));
                float acc = 0.0f;
#pragma unroll
                for (int j = NT; j >= 1; --j)            // descending lag
                    if (w & (1u << (NT - j))) acc = __fadd_rn(acc, kk[j]);
                dst[dt * (HR * 72)] = acc;
            }
        }
        __syncthreads();

        // ---- consume: Winograd + spike scan, 4 outputs per thread ----
#pragma unroll 2
        for (int dt = 0; dt < TC; ++dt) {
            int t = tb + dt;

            float rx[4][4];
#pragma unroll
            for (int r = 0; r < 4; ++r) {
                float2 a = *(const float2*)&s_buf[dt][row0 + r][col0];
                float2 c = *(const float2*)&s_buf[dt][row0 + r][col0 + 2];
                rx[r][0] = a.x; rx[r][1] = a.y; rx[r][2] = c.x; rx[r][3] = c.y;
            }

            float tt[4][4];
#pragma unroll
            for (int c = 0; c < 4; ++c) {
                tt[0][c] = __fsub_rn(rx[0][c], rx[2][c]);
                tt[1][c] = __fadd_rn(rx[1][c], rx[2][c]);
                tt[2][c] = __fsub_rn(rx[2][c], rx[1][c]);
                tt[3][c] = __fsub_rn(rx[1][c], rx[3][c]);
            }

            float s0[4], s1[4];
#pragma unroll
            for (int j = 0; j < 4; ++j) {
                float M[4];
#pragma unroll
                for (int i = 0; i < 4; ++i) {
                    float t0 = tt[i][0], t1 = tt[i][1], t2 = tt[i][2], t3 = tt[i][3];
                    float Vij = (j == 0) ? __fsub_rn(t0, t2)
                              : (j == 1) ? __fadd_rn(t1, t2)
                              : (j == 2) ? __fsub_rn(t2, t1)
                                         : __fsub_rn(t1, t3);
                    M[i] = __fmul_rn(U[i][j], Vij);
                }
                s0[j] = __fadd_rn(__fadd_rn(M[0], M[1]), M[2]);
                s1[j] = __fsub_rn(__fsub_rn(M[1], M[2]), M[3]);
            }
            float y[4];
            y[0] = __fadd_rn(__fadd_rn(s0[0], s0[1]), s0[2]);   // (0,0)
            y[1] = __fsub_rn(__fsub_rn(s0[1], s0[2]), s0[3]);   // (0,1)
            y[2] = __fadd_rn(__fadd_rn(s1[0], s1[1]), s1[2]);   // (1,0)
            y[3] = __fsub_rn(__fsub_rn(s1[1], s1[2]), s1[3]);   // (1,1)

            // ---- refractory: IIR fast path + warp-voted exact fallback ----
            float rnew[4];
            bool  sp[4];
            bool  band = false;
#pragma unroll
            for (int p = 0; p < 4; ++p) {
                float rt = fmaf(A1, r1[p], fmaf(A2, r2[p], __fmul_rn(RK1, sf[p])));
                rnew[p]  = rt;
                float d  = __fsub_rn(__fadd_rn(y[p], rt), THETA);
                sp[p]    = (d > 0.0f);
                band    |= (fabsf(d) <= EPS);
            }
            if (__ballot_sync(0xffffffffu, band)) {
                // uniform warp branch: exact descending-j sums (reference order)
#pragma unroll
                for (int p = 0; p < 4; ++p) {
                    float r = 0.0f;
#pragma unroll
                    for (int j = JMAX; j >= 1; --j)       // s_rk[j]: broadcast LDS
                        if ((win[p] >> (j - 1)) & 1ull) r = __fadd_rn(r, s_rk[j]);
                    sp[p] = (__fadd_rn(y[p], r) >= THETA);
                }
            }
#pragma unroll
            for (int p = 0; p < 4; ++p) {
                unsigned long long spb = sp[p] ? 1ull : 0ull;
                sm[p]  |= spb << t;
                win[p]  = (win[p] << 1) | spb;
                r2[p] = r1[p];
                r1[p] = rnew[p];
                sf[p] = sp[p] ? 1.0f : 0.0f;
            }
        }
        __syncthreads();
    }

    // ---- epilogue ----
#pragma unroll
    for (int p = 0; p < 4; ++p) {
        const int h   = h0 + 2 * tr + (p >> 1);
        const int wc  = 2 * tcix + (p & 1);
        const int loc = (b * H_ + h) * W_ + wc;
        if (LAYER == 0) {
            g_s1bits[loc] = sm[p];
        } else {
            float4* o = (float4*)(out + (size_t)loc * T_);
            const unsigned long long sv = sm[p];
#pragma unroll
            for (int i = 0; i < 16; ++i) {
                float4 v;
                v.x = ((sv >> (4 * i + 0)) & 1ull) ? 1.0f : 0.0f;
                v.y = ((sv >> (4 * i + 1)) & 1ull) ? 1.0f : 0.0f;
                v.z = ((sv >> (4 * i + 2)) & 1ull) ? 1.0f : 0.0f;
                v.w = ((sv >> (4 * i + 3)) & 1ull) ? 1.0f : 0.0f;
                o[i] = v;
            }
        }
    }
}

// ---------------------------------------------------------------------------
extern "C" void kernel_launch(void* const* d_in, const int* in_sizes, int n_in,
                              void* d_out, int out_size) {
    const float* x  = (const float*)d_in[0];
    const float* w1 = (const float*)d_in[1];
    const float* w2 = (const float*)d_in[2];
    float* out = (float*)d_out;

    dim3 pblk(64, 4), pgrd(H_ / 4, B_);
    pack_kernel<<<pgrd, pblk>>>(x);

    dim3 fblk(128), fgrd(H_ / 8, B_);
    fused_kernel<0><<<fgrd, fblk>>>(w1, nullptr);
    fused_kernel<1><<<fgrd, fblk>>>(w2, out);
}

// round 17
// speedup vs baseline: 1.0835x; 1.0835x over previous
#include <cuda_runtime.h>
#include <math.h>

#define B_   16
#define H_   128
#define W_   64
#define T_   64
#define NLOC (B_ * H_ * W_)

typedef unsigned long long u64;

// f32x2 packed helpers (SASS: FADD2/FMUL2; per-lane IEEE rn == scalar ops)
__device__ __forceinline__ u64 f2add(u64 a, u64 b) {
    u64 r; asm("add.rn.f32x2 %0, %1, %2;" : "=l"(r) : "l"(a), "l"(b)); return r;
}
__device__ __forceinline__ u64 f2sub(u64 a, u64 b) {
    u64 r; asm("sub.rn.f32x2 %0, %1, %2;" : "=l"(r) : "l"(a), "l"(b)); return r;
}
__device__ __forceinline__ u64 f2mul(u64 a, u64 b) {
    u64 r; asm("mul.rn.f32x2 %0, %1, %2;" : "=l"(r) : "l"(a), "l"(b)); return r;
}
__device__ __forceinline__ u64 f2pack(float lo, float hi) {
    u64 r; asm("mov.b64 %0, {%1, %2};" : "=l"(r) : "f"(lo), "f"(hi)); return r;
}
__device__ __forceinline__ void f2unpack(u64 v, float& lo, float& hi) {
    asm("mov.b64 {%0, %1}, %2;" : "=f"(lo), "=f"(hi) : "l"(v));
}

// Scratch: spike bitmasks (1 bit per timestep)
__device__ u64 g_xbits[NLOC];
__device__ u64 g_s1bits[NLOC];

// ---------------------------------------------------------------------------
// Kernel 0: pack input floats (exactly 0.0 / 1.0) into per-neuron bitmasks.
// ---------------------------------------------------------------------------
__global__ void __launch_bounds__(256) pack_kernel(const float* __restrict__ in) {
    const int lane = threadIdx.x & 31;
    const int w0   = threadIdx.x & 32;
    const int h    = blockIdx.x * 4 + threadIdx.y;
    const int b    = blockIdx.y;
    const int loc0 = (b * H_ + h) * W_ + w0;
    const size_t gbase = (size_t)loc0 * T_;

    unsigned lo = 0u, hi = 0u;
#pragma unroll
    for (int i = 0; i < 64; ++i) {
        float v = in[gbase + i * 32 + lane];
        unsigned bal = __ballot_sync(0xffffffffu, v != 0.0f);
        if (lane == (i >> 1)) {
            if (i & 1) hi = bal; else lo = bal;
        }
    }
    g_xbits[loc0 + lane] = ((u64)hi << 32) | (u64)lo;
}

// ---------------------------------------------------------------------------
// Fused layer kernel — R15 structure; ONE change: timestep pairs (t, t+1)
// are packed into f32x2 lanes through the Winograd transform (identical
// per-lane IEEE rn arithmetic -> bit-identical to the scalar sequence).
// psp fill: R15's exact 64-bit-shift descending-j form (scalar, bit-exact),
// stores pairs. Refractory: IIR(2) + warp-voted EXACT fallback (R15).
// ---------------------------------------------------------------------------
template <int LAYER>
__global__ void __launch_bounds__(128) fused_kernel(const float* __restrict__ wconv,
                                                    float* __restrict__ out) {
    constexpr int   FIRN  = (LAYER == 0) ? 8 : 16;
    constexpr int   JMAX  = (LAYER == 0) ? 17 : 35;
    constexpr float THETA = (LAYER == 0) ? 30.0f : 50.0f;
    constexpr float EPS   = 0.015625f;       // 2^-6, validated R13/R15
    constexpr int   HR    = 10;              // halo rows (8 + 2)
    constexpr int   HC    = 66;              // halo cols (64 + 2)
    constexpr int   NH    = HR * HC;         // 660
    constexpr int   TC    = 8;               // timestep chunk (4 pairs)

    __shared__ __align__(16) float s_buf[TC / 2][HR][72][2];  // (t0,t1) pairs
    __shared__ float s_kk[FIRN];
    __shared__ float s_rk[JMAX + 1];
    __shared__ float s_w[9];

    const int tid = threadIdx.x;
    const int h0  = blockIdx.x * 8;
    const int b   = blockIdx.y;

    // --- taps in double, matching numpy exactly ---
    {
        const double tau   = (LAYER == 0) ? 1.0 : 2.0;
        const double rmult = (LAYER == 0) ? -60.0 : -100.0;  // -2*theta*scale_ref
        if (tid < FIRN) {
            double td = (double)tid;
            s_kk[tid] = (float)(((1.0 * td) / tau) * exp(1.0 - td / tau));
        }
        if (tid <= JMAX) {
            double td = (double)tid;
            double v  = ((rmult * td) / tau) * exp(1.0 - td / tau);
            s_rk[tid] = (tid == 0) ? 0.0f : (float)v;
        }
        if (tid < 9) s_w[tid] = wconv[tid];
    }
    __syncthreads();

    // IIR constants (approximation only; decisions guarded by ε-band)
    const double a_d = exp((LAYER == 0) ? -1.0 : -0.5);
    const float  A1  = (float)(2.0 * a_d);
    const float  A2  = (float)(-a_d * a_d);
    const float  RK1 = s_rk[1];

    float kk[FIRN];
#pragma unroll
    for (int k = 0; k < FIRN; ++k) kk[k] = s_kk[k];

    // --- weight transform U = G g G^T, exact-half form (identical to R6),
    //     then packed (u,u) for f32x2 multiplies ---
    u64 Up[4][4];
    {
        float q[4][3];
#pragma unroll
        for (int j = 0; j < 3; ++j) {
            float g0 = s_w[j], g1 = s_w[3 + j], g2 = s_w[6 + j];
            float s  = __fadd_rn(g0, g2);
            q[0][j] = g0;
            q[1][j] = __fmul_rn(0.5f, __fadd_rn(s, g1));
            q[2][j] = __fmul_rn(0.5f, __fsub_rn(s, g1));
            q[3][j] = g2;
        }
#pragma unroll
        for (int i = 0; i < 4; ++i) {
            float q0 = q[i][0], q1 = q[i][1], q2 = q[i][2];
            float s  = __fadd_rn(q0, q2);
            float u0 = q0;
            float u1 = __fmul_rn(0.5f, __fadd_rn(s, q1));
            float u2 = __fmul_rn(0.5f, __fsub_rn(s, q1));
            float u3 = q2;
            Up[i][0] = f2pack(u0, u0);
            Up[i][1] = f2pack(u1, u1);
            Up[i][2] = f2pack(u2, u2);
            Up[i][3] = f2pack(u3, u3);
        }
    }

    // --- halo bitmask load: rows h0-1..h0+8, cols -1..64, zeros outside ---
    const u64* bits = (LAYER == 0) ? g_xbits : g_s1bits;
    u64 hm[6];
    int soff[6];
#pragma unroll
    for (int k = 0; k < 6; ++k) {
        int l  = tid + 128 * k;
        int hr = l / HC, hc = l % HC;
        bool valid = (l < NH);
        int grow = h0 - 1 + hr, gcol = hc - 1;
        u64 v = 0ull;
        if (valid && (unsigned)grow < (unsigned)H_ && (unsigned)gcol < (unsigned)W_)
            v = bits[(b * H_ + grow) * W_ + gcol];
        hm[k]   = v;
        soff[k] = valid ? hr * 72 + hc : 9 * 72 + 66;   // pad slot if invalid
    }

    const int tr   = tid >> 5;           // tile row 0..3
    const int tcix = tid & 31;           // tile col 0..31
    const int row0 = 2 * tr;
    const int col0 = 2 * tcix;

    u64 sm[4]  = {0ull, 0ull, 0ull, 0ull};
    u64 win[4] = {0ull, 0ull, 0ull, 0ull};
    float r1[4] = {0.0f, 0.0f, 0.0f, 0.0f};
    float r2[4] = {0.0f, 0.0f, 0.0f, 0.0f};
    float sf[4] = {0.0f, 0.0f, 0.0f, 0.0f};

    for (int tb = 0; tb < T_; tb += TC) {
        // ---- psp fill: R15 exact form (descending lag j), stored as pairs ----
#pragma unroll
        for (int k = 0; k < 6; ++k) {
            u64 mk = hm[k];
            float* dst = &s_buf[0][0][0][0] + soff[k] * 2;
#pragma unroll
            for (int dtp = 0; dtp < TC / 2; ++dtp) {
                float accs[2];
#pragma unroll
                for (int par = 0; par < 2; ++par) {
                    int t = tb + 2 * dtp + par;
                    u64 mt = mk << (63 - t);             // bit 63-j == spike t-j
                    float acc = 0.0f;
#pragma unroll
                    for (int ki = 0; ki < FIRN - 1; ++ki) {
                        int j = FIRN - 1 - ki;           // descending lag
                        if ((mt >> (63 - j)) & 1ull) acc = __fadd_rn(acc, kk[j]);
                    }
                    accs[par] = acc;
                }
                *(u64*)(dst + dtp * (HR * 72 * 2)) = f2pack(accs[0], accs[1]);
            }
        }
        __syncthreads();

        // ---- consume: f32x2 Winograd over t-pairs + scalar spike scan ----
#pragma unroll 2
        for (int dtp = 0; dtp < TC / 2; ++dtp) {
            u64 rxp[4][4];
#pragma unroll
            for (int r = 0; r < 4; ++r)
#pragma unroll
                for (int c = 0; c < 4; ++c)
                    rxp[r][c] = *(const u64*)&s_buf[dtp][row0 + r][col0 + c][0];

            u64 ttp[4][4];
#pragma unroll
            for (int c = 0; c < 4; ++c) {
                ttp[0][c] = f2sub(rxp[0][c], rxp[2][c]);
                ttp[1][c] = f2add(rxp[1][c], rxp[2][c]);
                ttp[2][c] = f2sub(rxp[2][c], rxp[1][c]);
                ttp[3][c] = f2sub(rxp[1][c], rxp[3][c]);
            }

            u64 s0p[4], s1p[4];
#pragma unroll
            for (int j = 0; j < 4; ++j) {
                u64 M[4];
#pragma unroll
                for (int i = 0; i < 4; ++i) {
                    u64 Vij = (j == 0) ? f2sub(ttp[i][0], ttp[i][2])
                            : (j == 1) ? f2add(ttp[i][1], ttp[i][2])
                            : (j == 2) ? f2sub(ttp[i][2], ttp[i][1])
                                       : f2sub(ttp[i][1], ttp[i][3]);
                    M[i] = f2mul(Up[i][j], Vij);
                }
                s0p[j] = f2add(f2add(M[0], M[1]), M[2]);
                s1p[j] = f2sub(f2sub(M[1], M[2]), M[3]);
            }
            u64 yp[4];
            yp[0] = f2add(f2add(s0p[0], s0p[1]), s0p[2]);   // (0,0)
            yp[1] = f2sub(f2sub(s0p[1], s0p[2]), s0p[3]);   // (0,1)
            yp[2] = f2add(f2add(s1p[0], s1p[1]), s1p[2]);   // (1,0)
            yp[3] = f2sub(f2sub(s1p[1], s1p[2]), s1p[3]);   // (1,1)

            float ylo[4], yhi[4];
#pragma unroll
            for (int p = 0; p < 4; ++p) f2unpack(yp[p], ylo[p], yhi[p]);

            // two sequential scan steps (t0 then t1)
#pragma unroll
            for (int half = 0; half < 2; ++half) {
                const int t = tb + 2 * dtp + half;
                float rnew[4];
                bool  sp[4];
                bool  band = false;
#pragma unroll
                for (int p = 0; p < 4; ++p) {
                    float y  = half ? yhi[p] : ylo[p];
                    float rt = fmaf(A1, r1[p], fmaf(A2, r2[p], __fmul_rn(RK1, sf[p])));
                    rnew[p]  = rt;
                    float d  = __fsub_rn(__fadd_rn(y, rt), THETA);
                    sp[p]    = (d > 0.0f);
                    band    |= (fabsf(d) <= EPS);
                }
                if (__ballot_sync(0xffffffffu, band)) {
                    // uniform warp branch: exact descending-j sums (ref order)
#pragma unroll
                    for (int p = 0; p < 4; ++p) {
                        float y = half ? yhi[p] : ylo[p];
                        float r = 0.0f;
#pragma unroll
                        for (int j = JMAX; j >= 1; --j)   // s_rk[j]: broadcast LDS
                            if ((win[p] >> (j - 1)) & 1ull) r = __fadd_rn(r, s_rk[j]);
                        sp[p] = (__fadd_rn(y, r) >= THETA);
                    }
                }
#pragma unroll
                for (int p = 0; p < 4; ++p) {
                    u64 spb = sp[p] ? 1ull : 0ull;
                    sm[p]  |= spb << t;
                    win[p]  = (win[p] << 1) | spb;
                    r2[p] = r1[p];
                    r1[p] = rnew[p];
                    sf[p] = sp[p] ? 1.0f : 0.0f;
                }
            }
        }
        __syncthreads();
    }

    // ---- epilogue ----
#pragma unroll
    for (int p = 0; p < 4; ++p) {
        const int h   = h0 + 2 * tr + (p >> 1);
        const int wc  = 2 * tcix + (p & 1);
        const int loc = (b * H_ + h) * W_ + wc;
        if (LAYER == 0) {
            g_s1bits[loc] = sm[p];
        } else {
            float4* o = (float4*)(out + (size_t)loc * T_);
            const u64 sv = sm[p];
#pragma unroll
            for (int i = 0; i < 16; ++i) {
                float4 v;
                v.x = ((sv >> (4 * i + 0)) & 1ull) ? 1.0f : 0.0f;
                v.y = ((sv >> (4 * i + 1)) & 1ull) ? 1.0f : 0.0f;
                v.z = ((sv >> (4 * i + 2)) & 1ull) ? 1.0f : 0.0f;
                v.w = ((sv >> (4 * i + 3)) & 1ull) ? 1.0f : 0.0f;
                o[i] = v;
            }
        }
    }
}

// ---------------------------------------------------------------------------
extern "C" void kernel_launch(void* const* d_in, const int* in_sizes, int n_in,
                              void* d_out, int out_size) {
    const float* x  = (const float*)d_in[0];
    const float* w1 = (const float*)d_in[1];
    const float* w2 = (const float*)d_in[2];
    float* out = (float*)d_out;

    dim3 pblk(64, 4), pgrd(H_ / 4, B_);
    pack_kernel<<<pgrd, pblk>>>(x);

    dim3 fblk(128), fgrd(H_ / 8, B_);
    fused_kernel<0><<<fgrd, fblk>>>(w1, nullptr);
    fused_kernel<1><<<fgrd, fblk>>>(w2, out);
}